// round 5
// baseline (speedup 1.0000x reference)
#include <cuda_runtime.h>

// ---------------------------------------------------------------------------
#define B_ROWS   2048
#define NFEAT    128
#define NCOLS    256
#define K_TOTAL  50000
#define KPAD     50560      // >= 30000 + 8*2560, multiple of 64, pad zero-filled
#define U_DIM    10000
#define X_DIM    20000
#define KCHUNK   2560
#define KSTEP    128
#define SMEM_DYN 132096     // 2 x 64KB B buffers + 1KB align slack

// ---------------------------------------------------------------------------
__device__ unsigned short BT_hi[(size_t)NCOLS * KPAD];   // [V|T]^T bf16 hi, K-major
__device__ unsigned short BT_lo[(size_t)NCOLS * KPAD];   // bf16 lo plane
__device__ float g_acc[(size_t)3 * B_ROWS * NCOLS];      // [S|P|N][row][col]
__device__ float g_scal[3 * B_ROWS * 8];                 // [dst][row][vv,tt,vt,W,sum]
__device__ float4 g_gram4[K_TOTAL];                      // (vv, tt, vt, W) per k

// ---------------------------------------------------------------------------
__device__ __forceinline__ unsigned smem_u32(const void* p) {
    unsigned r;
    asm("{ .reg .u64 t; cvta.to.shared.u64 t, %1; cvt.u32.u64 %0, t; }" : "=r"(r) : "l"(p));
    return r;
}
__device__ __forceinline__ void split2(float f0, float f1, unsigned& h, unsigned& l) {
    unsigned b0 = __float_as_uint(f0), b1 = __float_as_uint(f1);
    h = __byte_perm(b0, b1, 0x7632);
    float l0 = f0 - __uint_as_float(b0 & 0xFFFF0000u);
    float l1 = f1 - __uint_as_float(b1 & 0xFFFF0000u);
    l = __byte_perm(__float_as_uint(l0), __float_as_uint(l1), 0x7632);
}
__device__ __forceinline__ void ldsm4(unsigned* r, unsigned a) {
    asm volatile("ldmatrix.sync.aligned.m8n8.x4.shared.b16 {%0,%1,%2,%3}, [%4];"
                 : "=r"(r[0]), "=r"(r[1]), "=r"(r[2]), "=r"(r[3]) : "r"(a));
}
__device__ __forceinline__ void mma16816(float* c, const unsigned* a, const unsigned* b) {
    asm volatile("mma.sync.aligned.m16n8k16.row.col.f32.bf16.bf16.f32 "
                 "{%0,%1,%2,%3}, {%4,%5,%6,%7}, {%8,%9}, {%0,%1,%2,%3};"
                 : "+f"(c[0]), "+f"(c[1]), "+f"(c[2]), "+f"(c[3])
                 : "r"(a[0]), "r"(a[1]), "r"(a[2]), "r"(a[3]), "r"(b[0]), "r"(b[1]));
}

// ---------------------------------------------------------------------------
__global__ void zero_kernel() {
    size_t idx = (size_t)blockIdx.x * blockDim.x + threadIdx.x;
    size_t n = (size_t)3 * B_ROWS * NCOLS;
    for (size_t i = idx; i < n; i += (size_t)gridDim.x * blockDim.x) g_acc[i] = 0.f;
    if (idx < 3 * B_ROWS * 8) g_scal[idx] = 0.f;
}

// ---------------------------------------------------------------------------
__global__ void gram_kernel(const float* __restrict__ V, const float* __restrict__ T,
                            const float* __restrict__ W) {
    int warp = threadIdx.x >> 5, lane = threadIdx.x & 31;
    int k = blockIdx.x * 8 + warp;
    if (k >= K_TOTAL) return;
    float4 v = reinterpret_cast<const float4*>(V + (size_t)k * NFEAT)[lane];
    float4 t = reinterpret_cast<const float4*>(T + (size_t)k * NFEAT)[lane];
    float vv = v.x*v.x + v.y*v.y + v.z*v.z + v.w*v.w;
    float tt = t.x*t.x + t.y*t.y + t.z*t.z + t.w*t.w;
    float vt = v.x*t.x + v.y*t.y + v.z*t.z + v.w*t.w;
#pragma unroll
    for (int o = 16; o; o >>= 1) {
        vv += __shfl_down_sync(0xffffffffu, vv, o);
        tt += __shfl_down_sync(0xffffffffu, tt, o);
        vt += __shfl_down_sync(0xffffffffu, vt, o);
    }
    if (lane == 0) g_gram4[k] = make_float4(vv, tt, vt, W[k]);
}

// ---------------------------------------------------------------------------
// Transpose V/T into K-major bf16 hi/lo planes [256 x KPAD]; pad zero-filled.
__global__ void prep_vt(const float* __restrict__ V, const float* __restrict__ T) {
    __shared__ float tile[64][129];
    const float* S = blockIdx.y ? T : V;
    int nBase = blockIdx.y ? NFEAT : 0;
    int k0 = blockIdx.x * 64;
    int tid = threadIdx.x;
#pragma unroll
    for (int t = 0; t < 8; t++) {
        int idx = tid + t * 256;
        int r = idx >> 5, n4 = idx & 31;
        float4 v = make_float4(0.f, 0.f, 0.f, 0.f);
        if (k0 + r < K_TOTAL)
            v = *reinterpret_cast<const float4*>(S + (size_t)(k0 + r) * NFEAT + n4 * 4);
        tile[r][n4*4+0] = v.x; tile[r][n4*4+1] = v.y;
        tile[r][n4*4+2] = v.z; tile[r][n4*4+3] = v.w;
    }
    __syncthreads();
#pragma unroll
    for (int t = 0; t < 4; t++) {
        int idx = tid + t * 256;
        int n = idx >> 3, rq = idx & 7;
        int kk = k0 + rq * 8;
        unsigned hw[4], lw[4];
#pragma unroll
        for (int j = 0; j < 4; j++)
            split2(tile[rq*8 + 2*j][n], tile[rq*8 + 2*j + 1][n], hw[j], lw[j]);
        size_t off = (size_t)(nBase + n) * KPAD + kk;
        *reinterpret_cast<uint4*>(BT_hi + off) = make_uint4(hw[0], hw[1], hw[2], hw[3]);
        *reinterpret_cast<uint4*>(BT_lo + off) = make_uint4(lw[0], lw[1], lw[2], lw[3]);
    }
}

// ---------------------------------------------------------------------------
// bf16 mma.sync split-K GEMM, A fragments loaded directly from gmem.
// grid = (28 kchunks, 16 mtiles, 2 ntiles), block = 256 (8 warps, 4m x 2n).
__global__ void __launch_bounds__(256, 1) gemm_kernel(
    const float* __restrict__ u, const float* __restrict__ xprev,
    const float* __restrict__ xpos, const float* __restrict__ xneg)
{
    extern __shared__ char dyn[];
    unsigned sraw = smem_u32(dyn);
    unsigned sb = (sraw + 1023u) & ~1023u;
    const unsigned buf0 = sb, buf1 = sb + 65536u;
    // per buf: [sub0: Bhi 16K | Blo 16K][sub1: Bhi | Blo]; sub = 64-k half

    const int tid = threadIdx.x;
    const int lane = tid & 31, warp = tid >> 5;
    const int wr = warp >> 1, wc = warp & 1;

    int kc = blockIdx.x;
    const float* A; int lda, kLen, segOff, accIdx, kcL;
    if (kc < 4)       { A = u;     lda = U_DIM; kLen = U_DIM; segOff = 0;             accIdx = 0; kcL = kc; }
    else if (kc < 12) { A = xprev; lda = X_DIM; kLen = X_DIM; segOff = U_DIM;         accIdx = 0; kcL = kc - 4; }
    else if (kc < 20) { A = xpos;  lda = X_DIM; kLen = X_DIM; segOff = U_DIM + X_DIM; accIdx = 1; kcL = kc - 12; }
    else              { A = xneg;  lda = X_DIM; kLen = X_DIM; segOff = U_DIM + X_DIM; accIdx = 2; kcL = kc - 20; }
    const int m0 = blockIdx.y * 128;
    const int nt0 = blockIdx.z;
    const int kStart = kcL * KCHUNK;
    const int kLenC = min(KCHUNK, kLen - kStart);   // always a multiple of 16
    const int nsteps = (kLenC + KSTEP - 1) / KSTEP;

    // ---- B cp.async mapping: 4096 16B tasks -> 16 per thread ----
    const unsigned short* bSrc[16]; unsigned bDst[16];
#pragma unroll
    for (int tt = 0; tt < 16; tt++) {
        int idx = tid + tt * 256;
        int plane = idx >> 11, sub = (idx >> 10) & 1, rn = (idx >> 3) & 127, kq = idx & 7;
        const unsigned short* base = plane ? BT_lo : BT_hi;
        bSrc[tt] = base + (size_t)(nt0 * 128 + rn) * KPAD + segOff + kStart + sub * 64 + kq * 8;
        unsigned off = rn * 128 + kq * 16;
        bDst[tt] = sub * 32768u + plane * 16384u + (off ^ ((off >> 3) & 0x70));
    }
    // ---- A fragment row pointers (rows wr*32 + {0,8,16,24} + lane/4) ----
    const float* aR[4];
#pragma unroll
    for (int j = 0; j < 4; j++)
        aR[j] = A + (size_t)(m0 + wr * 32 + j * 8 + (lane >> 2)) * lda + kStart + (lane & 3) * 2;
    // ---- B ldsm lane offsets ----
    unsigned bLd[4];
#pragma unroll
    for (int nj = 0; nj < 4; nj++)
        bLd[nj] = (unsigned)((wc*64 + nj*16 + ((lane >> 4) << 3) + (lane & 7)) * 128
                             + ((lane >> 3) & 1) * 16);
    // ---- scal mapping: 2 rows/thread, 16-k slice within this nt's 64-k half ----
    const int rG = tid >> 2, ksl = tid & 3;
    const int r0s = rG * 2;
    const int kOffS = nt0 * 64 + ksl * 16;
    const float* z0 = A + (size_t)(m0 + r0s) * lda + kStart + kOffS;
    const float* z1 = z0 + lda;
    const float4* gBase = g_gram4 + segOff + kStart + kOffS;

    float c[2][8][4];
#pragma unroll
    for (int i = 0; i < 2; i++)
#pragma unroll
        for (int j = 0; j < 8; j++)
#pragma unroll
            for (int q = 0; q < 4; q++) c[i][j][q] = 0.f;
    float sA[5] = {0,0,0,0,0}, sB[5] = {0,0,0,0,0};

#define ISSUE_B(st, bufAdr) do {                                                 \
    int bo_ = (st) * KSTEP;                                                      \
    _Pragma("unroll")                                                            \
    for (int tt = 0; tt < 16; tt++) {                                            \
        unsigned d_ = (bufAdr) + bDst[tt];                                       \
        const void* s_ = (const void*)(bSrc[tt] + bo_);                          \
        asm volatile("cp.async.cg.shared.global [%0], [%1], 16;"                 \
                     :: "r"(d_), "l"(s_) : "memory");                            \
    }                                                                            \
} while (0)

#define COMPUTE_KK(kk, bufAdr, st) do {                                          \
    unsigned bB_ = (bufAdr) + ((kk) >> 2) * 32768u;                              \
    unsigned kL_ = ((kk) & 3) * 32u;                                             \
    unsigned bh_[4][4], bl_[4][4];                                               \
    _Pragma("unroll")                                                            \
    for (int nj = 0; nj < 4; nj++) {                                             \
        unsigned o_ = bLd[nj] + kL_, sw_ = o_ ^ ((o_ >> 3) & 0x70);              \
        ldsm4(bh_[nj], bB_ + sw_); ldsm4(bl_[nj], bB_ + 16384u + sw_);           \
    }                                                                            \
    unsigned ah_[2][4], al_[2][4];                                               \
    int ko_ = (st) * KSTEP + (kk) * 16;                                          \
    _Pragma("unroll")                                                            \
    for (int mi = 0; mi < 2; mi++) {                                             \
        const float* p_ = aR[2*mi]   + ko_;                                      \
        const float* q_ = aR[2*mi+1] + ko_;                                      \
        float2 f0 = *reinterpret_cast<const float2*>(p_);                        \
        float2 f1 = *reinterpret_cast<const float2*>(q_);                        \
        float2 f2 = *reinterpret_cast<const float2*>(p_ + 8);                    \
        float2 f3 = *reinterpret_cast<const float2*>(q_ + 8);                    \
        split2(f0.x, f0.y, ah_[mi][0], al_[mi][0]);                              \
        split2(f1.x, f1.y, ah_[mi][1], al_[mi][1]);                              \
        split2(f2.x, f2.y, ah_[mi][2], al_[mi][2]);                              \
        split2(f3.x, f3.y, ah_[mi][3], al_[mi][3]);                              \
    }                                                                            \
    _Pragma("unroll")                                                            \
    for (int mi = 0; mi < 2; mi++)                                               \
    _Pragma("unroll")                                                            \
    for (int nj = 0; nj < 4; nj++)                                               \
    _Pragma("unroll")                                                            \
    for (int h = 0; h < 2; h++) {                                                \
        float* cc = c[mi][nj * 2 + h];                                           \
        mma16816(cc, ah_[mi], &bh_[nj][h * 2]);                                  \
        mma16816(cc, ah_[mi], &bl_[nj][h * 2]);                                  \
        mma16816(cc, al_[mi], &bh_[nj][h * 2]);                                  \
    }                                                                            \
} while (0)

    // prologue: fill two B stages
    ISSUE_B(0, buf0);
    asm volatile("cp.async.commit_group;" ::: "memory");
    if (nsteps > 1) ISSUE_B(1, buf1);
    asm volatile("cp.async.commit_group;" ::: "memory");

    for (int st = 0; st < nsteps; st++) {
        asm volatile("cp.async.wait_group 1;" ::: "memory");
        __syncthreads();
        unsigned bufAdr = (st & 1) ? buf1 : buf0;
        int kkEnd = min(8, (kLenC - st * KSTEP) >> 4);

        // scal: z . {vv,tt,vt,W,1} over this thread's 16-k slice
#pragma unroll
        for (int j = 0; j < 4; j++) {
            int kk_ = st * KSTEP + kOffS + j * 4;
            if (kk_ < kLenC) {
                float4 za = *reinterpret_cast<const float4*>(z0 + st * KSTEP + j * 4);
                float4 zb = *reinterpret_cast<const float4*>(z1 + st * KSTEP + j * 4);
                const float4* g = gBase + st * KSTEP + j * 4 - kOffS + kOffS; // = gBase + st*KSTEP + j*4
#pragma unroll
                for (int e = 0; e < 4; e++) {
                    float4 gr = g[e];
                    float ze = (e == 0) ? za.x : (e == 1) ? za.y : (e == 2) ? za.z : za.w;
                    float zf = (e == 0) ? zb.x : (e == 1) ? zb.y : (e == 2) ? zb.z : zb.w;
                    sA[0] += ze * gr.x; sA[1] += ze * gr.y; sA[2] += ze * gr.z;
                    sA[3] += ze * gr.w; sA[4] += ze;
                    sB[0] += zf * gr.x; sB[1] += zf * gr.y; sB[2] += zf * gr.z;
                    sB[3] += zf * gr.w; sB[4] += zf;
                }
            }
        }

        if (kkEnd == 8) {
#pragma unroll
            for (int kk = 0; kk < 8; kk++) COMPUTE_KK(kk, bufAdr, st);
        } else {
            for (int kk = 0; kk < kkEnd; kk++) COMPUTE_KK(kk, bufAdr, st);
        }
        __syncthreads();
        if (st + 2 < nsteps) ISSUE_B(st + 2, bufAdr);
        asm volatile("cp.async.commit_group;" ::: "memory");
    }

    // ---- epilogue: atomic reduce C tile ----
    float* accBase = g_acc + (size_t)accIdx * B_ROWS * NCOLS;
    int colBase = nt0 * 128 + wc * 64;
#pragma unroll
    for (int mi = 0; mi < 2; mi++) {
        int r0 = m0 + wr * 32 + mi * 16 + (lane >> 2);
#pragma unroll
        for (int nt = 0; nt < 8; nt++) {
            int c0 = colBase + nt * 8 + (lane & 3) * 2;
            atomicAdd(accBase + (size_t)r0 * NCOLS + c0,           c[mi][nt][0]);
            atomicAdd(accBase + (size_t)r0 * NCOLS + c0 + 1,       c[mi][nt][1]);
            atomicAdd(accBase + (size_t)(r0 + 8) * NCOLS + c0,     c[mi][nt][2]);
            atomicAdd(accBase + (size_t)(r0 + 8) * NCOLS + c0 + 1, c[mi][nt][3]);
        }
    }
    // ---- scal reduce over the 4 ksl lanes, atomicAdd per row ----
#pragma unroll
    for (int i = 0; i < 5; i++) {
        sA[i] += __shfl_xor_sync(0xffffffffu, sA[i], 1);
        sA[i] += __shfl_xor_sync(0xffffffffu, sA[i], 2);
        sB[i] += __shfl_xor_sync(0xffffffffu, sB[i], 1);
        sB[i] += __shfl_xor_sync(0xffffffffu, sB[i], 2);
    }
    if (ksl == 0) {
        float* d0 = g_scal + (size_t)(accIdx * B_ROWS + m0 + r0s) * 8;
        float* d1 = d0 + 8;
#pragma unroll
        for (int i = 0; i < 5; i++) atomicAdd(d0 + i, sA[i]);
#pragma unroll
        for (int i = 0; i < 5; i++) atomicAdd(d1 + i, sB[i]);
    }
#undef ISSUE_B
#undef COMPUTE_KK
}

// ---------------------------------------------------------------------------
__global__ void final_kernel(const float* __restrict__ bias, float* __restrict__ out) {
    int warp = threadIdx.x >> 5, lane = threadIdx.x & 31;
    int row = blockIdx.x * 8 + warp;
    if (row >= B_ROWS) return;

    const float* aS = g_acc + (size_t)row * NCOLS;
    const float* aP = g_acc + ((size_t)B_ROWS + row) * NCOLS;
    const float* aN = g_acc + ((size_t)2 * B_ROWS + row) * NCOLS;

    float t5p = 0.f, t6p = 0.f, dgp = 0.f;
    float t5n = 0.f, t6n = 0.f, dgn = 0.f;
#pragma unroll
    for (int f = lane; f < NFEAT; f += 32) {
        float vs = aS[f],         vp = aP[f],         vn = aN[f];
        float ts = aS[NFEAT + f], tp = aP[NFEAT + f], tn = aN[NFEAT + f];
        float vxp = vs + vp, txp = ts + tp;
        float vxn = vs + vn, txn = ts + tn;
        t5p += vxp * vxp; t6p += txp * vxp; dgp += txp * txp;
        t5n += vxn * vxn; t6n += txn * vxn; dgn += txn * txn;
    }
#pragma unroll
    for (int o = 16; o; o >>= 1) {
        t5p += __shfl_down_sync(0xffffffffu, t5p, o);
        t6p += __shfl_down_sync(0xffffffffu, t6p, o);
        dgp += __shfl_down_sync(0xffffffffu, dgp, o);
        t5n += __shfl_down_sync(0xffffffffu, t5n, o);
        t6n += __shfl_down_sync(0xffffffffu, t6n, o);
        dgn += __shfl_down_sync(0xffffffffu, dgn, o);
    }
    if (lane == 0) {
        const float* sS = g_scal + (size_t)(0 * B_ROWS + row) * 8;
        const float* sP = g_scal + (size_t)(1 * B_ROWS + row) * 8;
        const float* sN = g_scal + (size_t)(2 * B_ROWS + row) * 8;

        float zvvp = sS[0] + sP[0], zttp = sS[1] + sP[1], zvtp = sS[2] + sP[2], zsp = sS[4] + sP[4];
        float zvvn = sS[0] + sN[0], zttn = sS[1] + sN[1], zvtn = sS[2] + sN[2], zsn = sS[4] + sN[4];
        float lin_neg = sS[3] + sN[3] + bias[0];

        float qp = 0.5f * (zsp * zvvp + 2.f * zsp * zttp + 2.f * zsp * zvtp
                           - 2.f * t5p - 2.f * t6p) - 0.5f * dgp;
        float qn = 0.5f * (zsn * zvvn + 2.f * zsn * zttn + 2.f * zsn * zvtn
                           - 2.f * t5n - 2.f * t6n) - 0.5f * dgn;

        out[row]          = lin_neg + qp;
        out[B_ROWS + row] = lin_neg + qn;
    }
}

// ---------------------------------------------------------------------------
extern "C" void kernel_launch(void* const* d_in, const int* in_sizes, int n_in,
                              void* d_out, int out_size) {
    const float* u     = (const float*)d_in[0];
    const float* xprev = (const float*)d_in[1];
    const float* xpos  = (const float*)d_in[2];
    const float* xneg  = (const float*)d_in[3];
    const float* V     = (const float*)d_in[4];
    const float* T     = (const float*)d_in[5];
    const float* W     = (const float*)d_in[6];
    const float* bias  = (const float*)d_in[7];
    float* out = (float*)d_out;

    cudaFuncSetAttribute(gemm_kernel, cudaFuncAttributeMaxDynamicSharedMemorySize, SMEM_DYN);

    zero_kernel<<<512, 256>>>();
    gram_kernel<<<(K_TOTAL + 7) / 8, 256>>>(V, T, W);
    prep_vt<<<dim3(KPAD / 64, 2), 256>>>(V, T);
    gemm_kernel<<<dim3(28, 16, 2), 256, SMEM_DYN>>>(u, xprev, xpos, xneg);
    final_kernel<<<B_ROWS / 8, 256>>>(bias, out);
}

// round 6
// speedup vs baseline: 1.1225x; 1.1225x over previous
#include <cuda_runtime.h>

// ---------------------------------------------------------------------------
#define B_ROWS   2048
#define NFEAT    128
#define NCOLS    256
#define K_TOTAL  50000
#define KPAD     50560      // multiple of 64, zero padded
#define U_DIM    10000
#define X_DIM    20000
#define KCHUNK   1280
#define KSTEP    64
#define STAGE_SZ 98304      // Ahi 16K | Alo 16K | Bhi 32K | Blo 32K
#define SMEM_DYN 197632     // 2 stages + 1KB align slack

// ---------------------------------------------------------------------------
__device__ unsigned short BT_hi[(size_t)NCOLS * KPAD];   // [V|T]^T bf16 hi, K-major
__device__ unsigned short BT_lo[(size_t)NCOLS * KPAD];
__device__ float g_acc[(size_t)3 * B_ROWS * NCOLS];
__device__ float g_scal[3 * B_ROWS * 8];
__device__ float4 g_gram4[K_TOTAL];                      // (vv, tt, vt, W)

// ---------------------------------------------------------------------------
__device__ __forceinline__ unsigned smem_u32(const void* p) {
    unsigned r;
    asm("{ .reg .u64 t; cvta.to.shared.u64 t, %1; cvt.u32.u64 %0, t; }" : "=r"(r) : "l"(p));
    return r;
}
__device__ __forceinline__ void split2(float f0, float f1, unsigned& h, unsigned& l) {
    unsigned b0 = __float_as_uint(f0), b1 = __float_as_uint(f1);
    h = __byte_perm(b0, b1, 0x7632);
    float l0 = f0 - __uint_as_float(b0 & 0xFFFF0000u);
    float l1 = f1 - __uint_as_float(b1 & 0xFFFF0000u);
    l = __byte_perm(__float_as_uint(l0), __float_as_uint(l1), 0x7632);
}
__device__ __forceinline__ void ldsm4(unsigned* r, unsigned a) {
    asm volatile("ldmatrix.sync.aligned.m8n8.x4.shared.b16 {%0,%1,%2,%3}, [%4];"
                 : "=r"(r[0]), "=r"(r[1]), "=r"(r[2]), "=r"(r[3]) : "r"(a));
}
__device__ __forceinline__ void mma16816(float* c, const unsigned* a, const unsigned* b) {
    asm volatile("mma.sync.aligned.m16n8k16.row.col.f32.bf16.bf16.f32 "
                 "{%0,%1,%2,%3}, {%4,%5,%6,%7}, {%8,%9}, {%0,%1,%2,%3};"
                 : "+f"(c[0]), "+f"(c[1]), "+f"(c[2]), "+f"(c[3])
                 : "r"(a[0]), "r"(a[1]), "r"(a[2]), "r"(a[3]), "r"(b[0]), "r"(b[1]));
}

// ---------------------------------------------------------------------------
__global__ void zero_kernel() {
    size_t idx = (size_t)blockIdx.x * blockDim.x + threadIdx.x;
    size_t n = (size_t)3 * B_ROWS * NCOLS;
    for (size_t i = idx; i < n; i += (size_t)gridDim.x * blockDim.x) g_acc[i] = 0.f;
    if (idx < 3 * B_ROWS * 8) g_scal[idx] = 0.f;
}

// ---------------------------------------------------------------------------
__global__ void gram_kernel(const float* __restrict__ V, const float* __restrict__ T,
                            const float* __restrict__ W) {
    int warp = threadIdx.x >> 5, lane = threadIdx.x & 31;
    int k = blockIdx.x * 8 + warp;
    if (k >= K_TOTAL) return;
    float4 v = reinterpret_cast<const float4*>(V + (size_t)k * NFEAT)[lane];
    float4 t = reinterpret_cast<const float4*>(T + (size_t)k * NFEAT)[lane];
    float vv = v.x*v.x + v.y*v.y + v.z*v.z + v.w*v.w;
    float tt = t.x*t.x + t.y*t.y + t.z*t.z + t.w*t.w;
    float vt = v.x*t.x + v.y*t.y + v.z*t.z + v.w*t.w;
#pragma unroll
    for (int o = 16; o; o >>= 1) {
        vv += __shfl_down_sync(0xffffffffu, vv, o);
        tt += __shfl_down_sync(0xffffffffu, tt, o);
        vt += __shfl_down_sync(0xffffffffu, vt, o);
    }
    if (lane == 0) g_gram4[k] = make_float4(vv, tt, vt, W[k]);
}

// ---------------------------------------------------------------------------
__global__ void prep_vt(const float* __restrict__ V, const float* __restrict__ T) {
    __shared__ float tile[64][129];
    const float* S = blockIdx.y ? T : V;
    int nBase = blockIdx.y ? NFEAT : 0;
    int k0 = blockIdx.x * 64;
    int tid = threadIdx.x;
#pragma unroll
    for (int t = 0; t < 8; t++) {
        int idx = tid + t * 256;
        int r = idx >> 5, n4 = idx & 31;
        float4 v = make_float4(0.f, 0.f, 0.f, 0.f);
        if (k0 + r < K_TOTAL)
            v = *reinterpret_cast<const float4*>(S + (size_t)(k0 + r) * NFEAT + n4 * 4);
        tile[r][n4*4+0] = v.x; tile[r][n4*4+1] = v.y;
        tile[r][n4*4+2] = v.z; tile[r][n4*4+3] = v.w;
    }
    __syncthreads();
#pragma unroll
    for (int t = 0; t < 4; t++) {
        int idx = tid + t * 256;
        int n = idx >> 3, rq = idx & 7;
        int kk = k0 + rq * 8;
        unsigned hw[4], lw[4];
#pragma unroll
        for (int j = 0; j < 4; j++)
            split2(tile[rq*8 + 2*j][n], tile[rq*8 + 2*j + 1][n], hw[j], lw[j]);
        size_t off = (size_t)(nBase + n) * KPAD + kk;
        *reinterpret_cast<uint4*>(BT_hi + off) = make_uint4(hw[0], hw[1], hw[2], hw[3]);
        *reinterpret_cast<uint4*>(BT_lo + off) = make_uint4(lw[0], lw[1], lw[2], lw[3]);
    }
}

// ---------------------------------------------------------------------------
// CTA tile 128x256, warps 2m x 4n (warp tile 64x64), bf16 3-product split.
// grid = (56 kchunks, 16 mtiles), 256 threads.
__global__ void __launch_bounds__(256, 1) gemm_kernel(
    const float* __restrict__ u, const float* __restrict__ xprev,
    const float* __restrict__ xpos, const float* __restrict__ xneg)
{
    extern __shared__ char dyn[];
    unsigned sraw = smem_u32(dyn);
    unsigned sb = (sraw + 1023u) & ~1023u;
    const unsigned buf0 = sb, buf1 = sb + STAGE_SZ;

    const int tid = threadIdx.x;
    const int lane = tid & 31, warp = tid >> 5;
    const int wr = warp >> 2, wc = warp & 3;   // 2m x 4n

    int kc = blockIdx.x;
    const float* A; int lda, kLen, segOff, accIdx, kcL;
    if (kc < 8)       { A = u;     lda = U_DIM; kLen = U_DIM; segOff = 0;             accIdx = 0; kcL = kc; }
    else if (kc < 24) { A = xprev; lda = X_DIM; kLen = X_DIM; segOff = U_DIM;         accIdx = 0; kcL = kc - 8; }
    else if (kc < 40) { A = xpos;  lda = X_DIM; kLen = X_DIM; segOff = U_DIM + X_DIM; accIdx = 1; kcL = kc - 24; }
    else              { A = xneg;  lda = X_DIM; kLen = X_DIM; segOff = U_DIM + X_DIM; accIdx = 2; kcL = kc - 40; }
    const int m0 = blockIdx.y * 128;
    const int kStart = kcL * KCHUNK;
    const int kLenC = min(KCHUNK, kLen - kStart);   // multiple of 16
    const int nsteps = (kLenC + KSTEP - 1) / KSTEP;

    // ---- B cp.async mapping: 4096 16B tasks (2 planes x 256 rows x 8 kq) ----
    const unsigned short* bSrc[16]; unsigned bDst[16];
#pragma unroll
    for (int tt = 0; tt < 16; tt++) {
        int idx = tid + tt * 256;
        int plane = idx >> 11, rn = (idx >> 3) & 255, kq = idx & 7;
        const unsigned short* base = plane ? BT_lo : BT_hi;
        bSrc[tt] = base + (size_t)rn * KPAD + segOff + kStart + kq * 8;
        unsigned off = rn * 128 + kq * 16;
        bDst[tt] = 32768u + plane * 32768u + (off ^ ((off >> 3) & 0x70));
    }
    // ---- A producer mapping: 1024 float4 per 32-k half; 4 tasks/thread ----
    const int aRow0 = tid >> 3, aC4 = tid & 7;           // rows aRow0 + 32t
    const long l32 = (long)32 * lda;
    const float* aP0 = A + (size_t)(m0 + aRow0) * lda + kStart + aC4 * 4;
    const unsigned aSts0 = aRow0 * 128 + aC4 * 8;        // + t*4096 + h*64, then swizzle
    const unsigned aMsk = ((unsigned)(aRow0 & 7)) << 4;

    // ---- ldsm offsets (pre-swizzle) + per-fragment masks ----
    unsigned aLd[4], aMk[4], bLd[4], bMk[4];
#pragma unroll
    for (int mi = 0; mi < 4; mi++) {
        int rowm = wr * 64 + mi * 16 + (lane & 15);
        aLd[mi] = rowm * 128 + (lane >> 4) * 16;
        aMk[mi] = ((unsigned)(rowm & 7)) << 4;
    }
#pragma unroll
    for (int nj = 0; nj < 4; nj++) {
        int rown = wc * 64 + nj * 16 + ((lane >> 4) << 3) + (lane & 7);
        bLd[nj] = rown * 128 + ((lane >> 3) & 1) * 16;
        bMk[nj] = ((unsigned)(rown & 7)) << 4;
    }
    // ---- scal mapping: 2 rows/thread, 16-k slice ----
    const int rG = tid >> 2, ksl = tid & 3;
    const int r0s = rG * 2;
    const int kOffS = ksl * 16;
    const float* z0 = A + (size_t)(m0 + r0s) * lda + kStart + kOffS;
    const float* z1 = z0 + lda;
    const float4* gBase = g_gram4 + segOff + kStart + kOffS;

    float c[4][8][4];
#pragma unroll
    for (int i = 0; i < 4; i++)
#pragma unroll
        for (int j = 0; j < 8; j++)
#pragma unroll
            for (int q = 0; q < 4; q++) c[i][j][q] = 0.f;
    float sA[5] = {0,0,0,0,0}, sB[5] = {0,0,0,0,0};
    float4 avH[4];

#define ISSUE_B(st, bufAdr) do {                                                 \
    int bo_ = (st) * KSTEP;                                                      \
    _Pragma("unroll")                                                            \
    for (int tt = 0; tt < 16; tt++) {                                            \
        unsigned d_ = (bufAdr) + bDst[tt];                                       \
        const void* s_ = (const void*)(bSrc[tt] + bo_);                          \
        asm volatile("cp.async.cg.shared.global [%0], [%1], 16;"                 \
                     :: "r"(d_), "l"(s_) : "memory");                            \
    }                                                                            \
} while (0)

#define LDGA(stA, h) do {                                                        \
    _Pragma("unroll")                                                            \
    for (int t = 0; t < 4; t++) {                                                \
        int ko_ = (stA) * KSTEP + (h) * 32 + aC4 * 4;                            \
        if (ko_ < kLenC)                                                         \
            avH[t] = *reinterpret_cast<const float4*>(aP0 + t * l32 + (stA) * KSTEP + (h) * 32); \
        else avH[t] = make_float4(0.f, 0.f, 0.f, 0.f);                           \
    }                                                                            \
} while (0)

#define STSA(bufAdr, h) do {                                                     \
    _Pragma("unroll")                                                            \
    for (int t = 0; t < 4; t++) {                                                \
        unsigned h01, l01, h23, l23;                                             \
        split2(avH[t].x, avH[t].y, h01, l01);                                    \
        split2(avH[t].z, avH[t].w, h23, l23);                                    \
        unsigned o_ = (aSts0 + t * 4096u + (h) * 64u) ^ aMsk;                    \
        asm volatile("st.shared.v2.u32 [%0], {%1,%2};"                           \
                     :: "r"((bufAdr) + o_), "r"(h01), "r"(h23) : "memory");      \
        asm volatile("st.shared.v2.u32 [%0], {%1,%2};"                           \
                     :: "r"((bufAdr) + 16384u + o_), "r"(l01), "r"(l23) : "memory"); \
    }                                                                            \
} while (0)

#define COMPUTE_KK(kk, bufAdr) do {                                              \
    unsigned bh_[4][4], bl_[4][4], ah_[4][4], al_[4][4];                         \
    _Pragma("unroll")                                                            \
    for (int nj = 0; nj < 4; nj++) {                                             \
        unsigned o_ = (bLd[nj] + (kk) * 32u) ^ bMk[nj];                          \
        ldsm4(bh_[nj], (bufAdr) + 32768u + o_);                                  \
        ldsm4(bl_[nj], (bufAdr) + 65536u + o_);                                  \
    }                                                                            \
    _Pragma("unroll")                                                            \
    for (int mi = 0; mi < 4; mi++) {                                             \
        unsigned o_ = (aLd[mi] + (kk) * 32u) ^ aMk[mi];                          \
        ldsm4(ah_[mi], (bufAdr) + o_);                                           \
        ldsm4(al_[mi], (bufAdr) + 16384u + o_);                                  \
    }                                                                            \
    _Pragma("unroll")                                                            \
    for (int mi = 0; mi < 4; mi++)                                               \
    _Pragma("unroll")                                                            \
    for (int nj = 0; nj < 4; nj++)                                               \
    _Pragma("unroll")                                                            \
    for (int h = 0; h < 2; h++) {                                                \
        float* cc = c[mi][nj * 2 + h];                                           \
        mma16816(cc, ah_[mi], &bh_[nj][h * 2]);                                  \
        mma16816(cc, ah_[mi], &bl_[nj][h * 2]);                                  \
        mma16816(cc, al_[mi], &bh_[nj][h * 2]);                                  \
    }                                                                            \
} while (0)

#define SCAL_STEP(st) do {                                                       \
    _Pragma("unroll")                                                            \
    for (int j = 0; j < 4; j++) {                                                \
        int kk_ = (st) * KSTEP + kOffS + j * 4;                                  \
        if (kk_ < kLenC) {                                                       \
            float4 za = *reinterpret_cast<const float4*>(z0 + (st) * KSTEP + j * 4); \
            float4 zb = *reinterpret_cast<const float4*>(z1 + (st) * KSTEP + j * 4); \
            const float4* g = gBase + (st) * KSTEP + j * 4;                      \
            _Pragma("unroll")                                                    \
            for (int e = 0; e < 4; e++) {                                        \
                float4 gr = g[e];                                                \
                float ze = (e == 0) ? za.x : (e == 1) ? za.y : (e == 2) ? za.z : za.w; \
                float zf = (e == 0) ? zb.x : (e == 1) ? zb.y : (e == 2) ? zb.z : zb.w; \
                sA[0] += ze * gr.x; sA[1] += ze * gr.y; sA[2] += ze * gr.z;      \
                sA[3] += ze * gr.w; sA[4] += ze;                                 \
                sB[0] += zf * gr.x; sB[1] += zf * gr.y; sB[2] += zf * gr.z;      \
                sB[3] += zf * gr.w; sB[4] += zf;                                 \
            }                                                                    \
        }                                                                        \
    }                                                                            \
} while (0)

    // ---- prologue ----
    ISSUE_B(0, buf0);
    asm volatile("cp.async.commit_group;" ::: "memory");
    if (nsteps > 1) ISSUE_B(1, buf1);
    asm volatile("cp.async.commit_group;" ::: "memory");
    LDGA(0, 0); STSA(buf0, 0);
    LDGA(0, 1); STSA(buf0, 1);

    for (int st = 0; st < nsteps; st++) {
        asm volatile("cp.async.wait_group 1;" ::: "memory");
        __syncthreads();
        unsigned bufC = (st & 1) ? buf1 : buf0;
        unsigned bufN = (st & 1) ? buf0 : buf1;
        bool pf = (st + 1) < nsteps;
        int kkEnd = min(4, (kLenC - st * KSTEP) >> 4);

        SCAL_STEP(st);
        if (kkEnd == 4) {
            if (pf) LDGA(st + 1, 0);
            COMPUTE_KK(0, bufC);
            COMPUTE_KK(1, bufC);
            if (pf) { STSA(bufN, 0); LDGA(st + 1, 1); }
            COMPUTE_KK(2, bufC);
            COMPUTE_KK(3, bufC);
            if (pf) STSA(bufN, 1);
        } else {
            // tail: st == nsteps-1, no prefetch needed
            for (int kk = 0; kk < kkEnd; kk++) COMPUTE_KK(kk, bufC);
        }
        __syncthreads();
        if (st + 2 < nsteps) ISSUE_B(st + 2, bufC);
        asm volatile("cp.async.commit_group;" ::: "memory");
    }

    // ---- epilogue: atomic reduce C ----
    float* accBase = g_acc + (size_t)accIdx * B_ROWS * NCOLS;
#pragma unroll
    for (int mi = 0; mi < 4; mi++) {
        int r0 = m0 + wr * 64 + mi * 16 + (lane >> 2);
#pragma unroll
        for (int jj = 0; jj < 8; jj++) {
            int c0 = wc * 64 + jj * 8 + (lane & 3) * 2;
            atomicAdd(accBase + (size_t)r0 * NCOLS + c0,           c[mi][jj][0]);
            atomicAdd(accBase + (size_t)r0 * NCOLS + c0 + 1,       c[mi][jj][1]);
            atomicAdd(accBase + (size_t)(r0 + 8) * NCOLS + c0,     c[mi][jj][2]);
            atomicAdd(accBase + (size_t)(r0 + 8) * NCOLS + c0 + 1, c[mi][jj][3]);
        }
    }
    // ---- scal reduce across 4 ksl lanes ----
#pragma unroll
    for (int i = 0; i < 5; i++) {
        sA[i] += __shfl_xor_sync(0xffffffffu, sA[i], 1);
        sA[i] += __shfl_xor_sync(0xffffffffu, sA[i], 2);
        sB[i] += __shfl_xor_sync(0xffffffffu, sB[i], 1);
        sB[i] += __shfl_xor_sync(0xffffffffu, sB[i], 2);
    }
    if (ksl == 0) {
        float* d0 = g_scal + (size_t)(accIdx * B_ROWS + m0 + r0s) * 8;
        float* d1 = d0 + 8;
#pragma unroll
        for (int i = 0; i < 5; i++) atomicAdd(d0 + i, sA[i]);
#pragma unroll
        for (int i = 0; i < 5; i++) atomicAdd(d1 + i, sB[i]);
    }
#undef ISSUE_B
#undef LDGA
#undef STSA
#undef COMPUTE_KK
#undef SCAL_STEP
}

// ---------------------------------------------------------------------------
__global__ void final_kernel(const float* __restrict__ bias, float* __restrict__ out) {
    int warp = threadIdx.x >> 5, lane = threadIdx.x & 31;
    int row = blockIdx.x * 8 + warp;
    if (row >= B_ROWS) return;

    const float* aS = g_acc + (size_t)row * NCOLS;
    const float* aP = g_acc + ((size_t)B_ROWS + row) * NCOLS;
    const float* aN = g_acc + ((size_t)2 * B_ROWS + row) * NCOLS;

    float t5p = 0.f, t6p = 0.f, dgp = 0.f;
    float t5n = 0.f, t6n = 0.f, dgn = 0.f;
#pragma unroll
    for (int f = lane; f < NFEAT; f += 32) {
        float vs = aS[f],         vp = aP[f],         vn = aN[f];
        float ts = aS[NFEAT + f], tp = aP[NFEAT + f], tn = aN[NFEAT + f];
        float vxp = vs + vp, txp = ts + tp;
        float vxn = vs + vn, txn = ts + tn;
        t5p += vxp * vxp; t6p += txp * vxp; dgp += txp * txp;
        t5n += vxn * vxn; t6n += txn * vxn; dgn += txn * txn;
    }
#pragma unroll
    for (int o = 16; o; o >>= 1) {
        t5p += __shfl_down_sync(0xffffffffu, t5p, o);
        t6p += __shfl_down_sync(0xffffffffu, t6p, o);
        dgp += __shfl_down_sync(0xffffffffu, dgp, o);
        t5n += __shfl_down_sync(0xffffffffu, t5n, o);
        t6n += __shfl_down_sync(0xffffffffu, t6n, o);
        dgn += __shfl_down_sync(0xffffffffu, dgn, o);
    }
    if (lane == 0) {
        const float* sS = g_scal + (size_t)(0 * B_ROWS + row) * 8;
        const float* sP = g_scal + (size_t)(1 * B_ROWS + row) * 8;
        const float* sN = g_scal + (size_t)(2 * B_ROWS + row) * 8;

        float zvvp = sS[0] + sP[0], zttp = sS[1] + sP[1], zvtp = sS[2] + sP[2], zsp = sS[4] + sP[4];
        float zvvn = sS[0] + sN[0], zttn = sS[1] + sN[1], zvtn = sS[2] + sN[2], zsn = sS[4] + sN[4];
        float lin_neg = sS[3] + sN[3] + bias[0];

        float qp = 0.5f * (zsp * zvvp + 2.f * zsp * zttp + 2.f * zsp * zvtp
                           - 2.f * t5p - 2.f * t6p) - 0.5f * dgp;
        float qn = 0.5f * (zsn * zvvn + 2.f * zsn * zttn + 2.f * zsn * zvtn
                           - 2.f * t5n - 2.f * t6n) - 0.5f * dgn;

        out[row]          = lin_neg + qp;
        out[B_ROWS + row] = lin_neg + qn;
    }
}

// ---------------------------------------------------------------------------
extern "C" void kernel_launch(void* const* d_in, const int* in_sizes, int n_in,
                              void* d_out, int out_size) {
    const float* u     = (const float*)d_in[0];
    const float* xprev = (const float*)d_in[1];
    const float* xpos  = (const float*)d_in[2];
    const float* xneg  = (const float*)d_in[3];
    const float* V     = (const float*)d_in[4];
    const float* T     = (const float*)d_in[5];
    const float* W     = (const float*)d_in[6];
    const float* bias  = (const float*)d_in[7];
    float* out = (float*)d_out;

    cudaFuncSetAttribute(gemm_kernel, cudaFuncAttributeMaxDynamicSharedMemorySize, SMEM_DYN);

    zero_kernel<<<512, 256>>>();
    gram_kernel<<<(K_TOTAL + 7) / 8, 256>>>(V, T, W);
    prep_vt<<<dim3(KPAD / 64, 2), 256>>>(V, T);
    gemm_kernel<<<dim3(56, 16), 256, SMEM_DYN>>>(u, xprev, xpos, xneg);
    final_kernel<<<B_ROWS / 8, 256>>>(bias, out);
}

// round 8
// speedup vs baseline: 1.2725x; 1.1336x over previous
#include <cuda_runtime.h>

// ---------------------------------------------------------------------------
#define B_ROWS   2048
#define NFEAT    128
#define NCOLS    256
#define K_TOTAL  50000
#define KPAD     50560      // multiple of 64, zero padded
#define U_DIM    10000
#define X_DIM    20000
#define KCHUNK   1280
#define KSTEP    64
#define STAGE_SZ 98304      // Ahi 16K | Alo 16K | Bhi 32K | Blo 32K
#define SMEM_DYN 197632     // 2 stages + 1KB align slack
#define NTHREADS 512

// ---------------------------------------------------------------------------
__device__ unsigned short BT_hi[(size_t)NCOLS * KPAD];   // [V|T]^T bf16 hi, K-major
__device__ unsigned short BT_lo[(size_t)NCOLS * KPAD];
__device__ float g_acc[(size_t)3 * B_ROWS * NCOLS];
__device__ float g_scal[3 * B_ROWS * 8];
__device__ float4 g_gram4[K_TOTAL];                      // (vv, tt, vt, W)

// ---------------------------------------------------------------------------
__device__ __forceinline__ unsigned smem_u32(const void* p) {
    unsigned r;
    asm("{ .reg .u64 t; cvta.to.shared.u64 t, %1; cvt.u32.u64 %0, t; }" : "=r"(r) : "l"(p));
    return r;
}
__device__ __forceinline__ void split2(float f0, float f1, unsigned& h, unsigned& l) {
    unsigned b0 = __float_as_uint(f0), b1 = __float_as_uint(f1);
    h = __byte_perm(b0, b1, 0x7632);
    float l0 = f0 - __uint_as_float(b0 & 0xFFFF0000u);
    float l1 = f1 - __uint_as_float(b1 & 0xFFFF0000u);
    l = __byte_perm(__float_as_uint(l0), __float_as_uint(l1), 0x7632);
}
__device__ __forceinline__ void ldsm4(unsigned* r, unsigned a) {
    asm volatile("ldmatrix.sync.aligned.m8n8.x4.shared.b16 {%0,%1,%2,%3}, [%4];"
                 : "=r"(r[0]), "=r"(r[1]), "=r"(r[2]), "=r"(r[3]) : "r"(a));
}
__device__ __forceinline__ void mma16816(float* c, const unsigned* a, const unsigned* b) {
    asm volatile("mma.sync.aligned.m16n8k16.row.col.f32.bf16.bf16.f32 "
                 "{%0,%1,%2,%3}, {%4,%5,%6,%7}, {%8,%9}, {%0,%1,%2,%3};"
                 : "+f"(c[0]), "+f"(c[1]), "+f"(c[2]), "+f"(c[3])
                 : "r"(a[0]), "r"(a[1]), "r"(a[2]), "r"(a[3]), "r"(b[0]), "r"(b[1]));
}

// ---------------------------------------------------------------------------
__global__ void zero_kernel() {
    size_t idx = (size_t)blockIdx.x * blockDim.x + threadIdx.x;
    size_t n = (size_t)3 * B_ROWS * NCOLS;
    for (size_t i = idx; i < n; i += (size_t)gridDim.x * blockDim.x) g_acc[i] = 0.f;
    if (idx < 3 * B_ROWS * 8) g_scal[idx] = 0.f;
}

// ---------------------------------------------------------------------------
__global__ void gram_kernel(const float* __restrict__ V, const float* __restrict__ T,
                            const float* __restrict__ W) {
    int warp = threadIdx.x >> 5, lane = threadIdx.x & 31;
    int k = blockIdx.x * 8 + warp;
    if (k >= K_TOTAL) return;
    float4 v = reinterpret_cast<const float4*>(V + (size_t)k * NFEAT)[lane];
    float4 t = reinterpret_cast<const float4*>(T + (size_t)k * NFEAT)[lane];
    float vv = v.x*v.x + v.y*v.y + v.z*v.z + v.w*v.w;
    float tt = t.x*t.x + t.y*t.y + t.z*t.z + t.w*t.w;
    float vt = v.x*t.x + v.y*t.y + v.z*t.z + v.w*t.w;
#pragma unroll
    for (int o = 16; o; o >>= 1) {
        vv += __shfl_down_sync(0xffffffffu, vv, o);
        tt += __shfl_down_sync(0xffffffffu, tt, o);
        vt += __shfl_down_sync(0xffffffffu, vt, o);
    }
    if (lane == 0) g_gram4[k] = make_float4(vv, tt, vt, W[k]);
}

// ---------------------------------------------------------------------------
__global__ void prep_vt(const float* __restrict__ V, const float* __restrict__ T) {
    __shared__ float tile[64][129];
    const float* S = blockIdx.y ? T : V;
    int nBase = blockIdx.y ? NFEAT : 0;
    int k0 = blockIdx.x * 64;
    int tid = threadIdx.x;
#pragma unroll
    for (int t = 0; t < 8; t++) {
        int idx = tid + t * 256;
        int r = idx >> 5, n4 = idx & 31;
        float4 v = make_float4(0.f, 0.f, 0.f, 0.f);
        if (k0 + r < K_TOTAL)
            v = *reinterpret_cast<const float4*>(S + (size_t)(k0 + r) * NFEAT + n4 * 4);
        tile[r][n4*4+0] = v.x; tile[r][n4*4+1] = v.y;
        tile[r][n4*4+2] = v.z; tile[r][n4*4+3] = v.w;
    }
    __syncthreads();
#pragma unroll
    for (int t = 0; t < 4; t++) {
        int idx = tid + t * 256;
        int n = idx >> 3, rq = idx & 7;
        int kk = k0 + rq * 8;
        unsigned hw[4], lw[4];
#pragma unroll
        for (int j = 0; j < 4; j++)
            split2(tile[rq*8 + 2*j][n], tile[rq*8 + 2*j + 1][n], hw[j], lw[j]);
        size_t off = (size_t)(nBase + n) * KPAD + kk;
        *reinterpret_cast<uint4*>(BT_hi + off) = make_uint4(hw[0], hw[1], hw[2], hw[3]);
        *reinterpret_cast<uint4*>(BT_lo + off) = make_uint4(lw[0], lw[1], lw[2], lw[3]);
    }
}

// ---------------------------------------------------------------------------
// CTA tile 128x256, 512 threads, 16 warps (4m x 4n), warp tile 32x64.
// scal (z.{vv,tt,vt,W,1}) fused into the A producer path.
// grid = (56 kchunks, 16 mtiles).
__global__ void __launch_bounds__(NTHREADS, 1) gemm_kernel(
    const float* __restrict__ u, const float* __restrict__ xprev,
    const float* __restrict__ xpos, const float* __restrict__ xneg)
{
    extern __shared__ char dyn[];
    unsigned sraw = smem_u32(dyn);
    unsigned sb = (sraw + 1023u) & ~1023u;
    const unsigned buf0 = sb, buf1 = sb + STAGE_SZ;

    const int tid = threadIdx.x;
    const int lane = tid & 31, warp = tid >> 5;
    const int wr = warp >> 2, wc = warp & 3;   // 4m x 4n

    int kc = blockIdx.x;
    const float* A; int lda, kLen, segOff, accIdx, kcL;
    if (kc < 8)       { A = u;     lda = U_DIM; kLen = U_DIM; segOff = 0;             accIdx = 0; kcL = kc; }
    else if (kc < 24) { A = xprev; lda = X_DIM; kLen = X_DIM; segOff = U_DIM;         accIdx = 0; kcL = kc - 8; }
    else if (kc < 40) { A = xpos;  lda = X_DIM; kLen = X_DIM; segOff = U_DIM + X_DIM; accIdx = 1; kcL = kc - 24; }
    else              { A = xneg;  lda = X_DIM; kLen = X_DIM; segOff = U_DIM + X_DIM; accIdx = 2; kcL = kc - 40; }
    const int m0 = blockIdx.y * 128;
    const int kStart = kcL * KCHUNK;
    const int kLenC = min(KCHUNK, kLen - kStart);   // multiple of 16
    const int nsteps = (kLenC + KSTEP - 1) / KSTEP;

    // ---- B cp.async mapping: 4096 16B tasks -> 8 per thread ----
    const unsigned short* bSrc[8]; unsigned bDst[8];
#pragma unroll
    for (int tt = 0; tt < 8; tt++) {
        int idx = tid + tt * NTHREADS;
        int plane = idx >> 11, rn = (idx >> 3) & 255, kq = idx & 7;
        const unsigned short* base = plane ? BT_lo : BT_hi;
        bSrc[tt] = base + (size_t)rn * KPAD + segOff + kStart + kq * 8;
        unsigned off = rn * 128 + kq * 16;
        bDst[tt] = 32768u + plane * 32768u + (off ^ ((off >> 3) & 0x70));
    }
    // ---- A producer mapping (fused scal): rows aRow0+{0,32,64,96}, 16 k-lanes ----
    const int aRow0 = tid >> 4, aC4 = tid & 15;
    const long l32 = (long)32 * lda;
    const float* aP0 = A + (size_t)(m0 + aRow0) * lda + kStart + aC4 * 4;
    const unsigned aSts0 = aRow0 * 128 + aC4 * 8;
    const unsigned aMsk = ((unsigned)(aRow0 & 7)) << 4;
    const float4* gP0 = g_gram4 + segOff + kStart + aC4 * 4;

    // ---- ldsm offsets (pre-swizzle) + masks ----
    unsigned aLd[2], aMk[2], bLd[4], bMk[4];
#pragma unroll
    for (int mi = 0; mi < 2; mi++) {
        int rowm = wr * 32 + mi * 16 + (lane & 15);
        aLd[mi] = rowm * 128 + (lane >> 4) * 16;
        aMk[mi] = ((unsigned)(rowm & 7)) << 4;
    }
#pragma unroll
    for (int nj = 0; nj < 4; nj++) {
        int rown = wc * 64 + nj * 16 + ((lane >> 4) << 3) + (lane & 7);
        bLd[nj] = rown * 128 + ((lane >> 3) & 1) * 16;
        bMk[nj] = ((unsigned)(rown & 7)) << 4;
    }

    float c[2][8][4];
#pragma unroll
    for (int i = 0; i < 2; i++)
#pragma unroll
        for (int j = 0; j < 8; j++)
#pragma unroll
            for (int q = 0; q < 4; q++) c[i][j][q] = 0.f;
    float sS[4][5];
#pragma unroll
    for (int t = 0; t < 4; t++)
#pragma unroll
        for (int i = 0; i < 5; i++) sS[t][i] = 0.f;
    float4 avH[2];

#define ISSUE_B(st, bufAdr) do {                                                 \
    int bo_ = (st) * KSTEP;                                                      \
    _Pragma("unroll")                                                            \
    for (int tt = 0; tt < 8; tt++) {                                             \
        unsigned d_ = (bufAdr) + bDst[tt];                                       \
        const void* s_ = (const void*)(bSrc[tt] + bo_);                          \
        asm volatile("cp.async.cg.shared.global [%0], [%1], 16;"                 \
                     :: "r"(d_), "l"(s_) : "memory");                            \
    }                                                                            \
} while (0)

// load rows {h*2, h*2+1} (i.e. +32*(2h), +32*(2h+1)) for step stA
#define LDGA(stA, h) do {                                                        \
    int ko_ = (stA) * KSTEP + aC4 * 4;                                           \
    _Pragma("unroll")                                                            \
    for (int t = 0; t < 2; t++) {                                                \
        if (ko_ < kLenC)                                                         \
            avH[t] = *reinterpret_cast<const float4*>(aP0 + ((h) * 2 + t) * l32 + (stA) * KSTEP); \
        else avH[t] = make_float4(0.f, 0.f, 0.f, 0.f);                           \
    }                                                                            \
} while (0)

// split + store rows {h*2, h*2+1}; fused scal accumulate
// gram index: gP0 is one float4 per k, already offset by aC4*4 -> step offset is stA*KSTEP
#define STSA(bufAdr, stA, h) do {                                                \
    int ko_ = (stA) * KSTEP + aC4 * 4;                                           \
    float4 gr_ = (ko_ < kLenC) ? gP0[(stA) * KSTEP]     : make_float4(0.f,0.f,0.f,0.f); \
    float4 g1_ = (ko_ < kLenC) ? gP0[(stA) * KSTEP + 1] : make_float4(0.f,0.f,0.f,0.f); \
    float4 g2_ = (ko_ < kLenC) ? gP0[(stA) * KSTEP + 2] : make_float4(0.f,0.f,0.f,0.f); \
    float4 g3_ = (ko_ < kLenC) ? gP0[(stA) * KSTEP + 3] : make_float4(0.f,0.f,0.f,0.f); \
    _Pragma("unroll")                                                            \
    for (int t = 0; t < 2; t++) {                                                \
        unsigned h01, l01, h23, l23;                                             \
        split2(avH[t].x, avH[t].y, h01, l01);                                    \
        split2(avH[t].z, avH[t].w, h23, l23);                                    \
        unsigned o_ = (aSts0 + ((h) * 2 + t) * 4096u) ^ aMsk;                    \
        asm volatile("st.shared.v2.u32 [%0], {%1,%2};"                           \
                     :: "r"((bufAdr) + o_), "r"(h01), "r"(h23) : "memory");      \
        asm volatile("st.shared.v2.u32 [%0], {%1,%2};"                           \
                     :: "r"((bufAdr) + 16384u + o_), "r"(l01), "r"(l23) : "memory"); \
        float* s_ = sS[(h) * 2 + t];                                             \
        s_[0] += avH[t].x * gr_.x; s_[1] += avH[t].x * gr_.y;                    \
        s_[2] += avH[t].x * gr_.z; s_[3] += avH[t].x * gr_.w; s_[4] += avH[t].x; \
        s_[0] += avH[t].y * g1_.x; s_[1] += avH[t].y * g1_.y;                    \
        s_[2] += avH[t].y * g1_.z; s_[3] += avH[t].y * g1_.w; s_[4] += avH[t].y; \
        s_[0] += avH[t].z * g2_.x; s_[1] += avH[t].z * g2_.y;                    \
        s_[2] += avH[t].z * g2_.z; s_[3] += avH[t].z * g2_.w; s_[4] += avH[t].z; \
        s_[0] += avH[t].w * g3_.x; s_[1] += avH[t].w * g3_.y;                    \
        s_[2] += avH[t].w * g3_.z; s_[3] += avH[t].w * g3_.w; s_[4] += avH[t].w; \
    }                                                                            \
} while (0)

#define COMPUTE_KK(kk, bufAdr) do {                                              \
    unsigned bh_[4][4], bl_[4][4], ah_[2][4], al_[2][4];                         \
    _Pragma("unroll")                                                            \
    for (int nj = 0; nj < 4; nj++) {                                             \
        unsigned o_ = (bLd[nj] + (kk) * 32u) ^ bMk[nj];                          \
        ldsm4(bh_[nj], (bufAdr) + 32768u + o_);                                  \
        ldsm4(bl_[nj], (bufAdr) + 65536u + o_);                                  \
    }                                                                            \
    _Pragma("unroll")                                                            \
    for (int mi = 0; mi < 2; mi++) {                                             \
        unsigned o_ = (aLd[mi] + (kk) * 32u) ^ aMk[mi];                          \
        ldsm4(ah_[mi], (bufAdr) + o_);                                           \
        ldsm4(al_[mi], (bufAdr) + 16384u + o_);                                  \
    }                                                                            \
    _Pragma("unroll")                                                            \
    for (int mi = 0; mi < 2; mi++)                                               \
    _Pragma("unroll")                                                            \
    for (int nj = 0; nj < 4; nj++)                                               \
    _Pragma("unroll")                                                            \
    for (int h = 0; h < 2; h++) {                                                \
        float* cc = c[mi][nj * 2 + h];                                           \
        mma16816(cc, ah_[mi], &bh_[nj][h * 2]);                                  \
        mma16816(cc, ah_[mi], &bl_[nj][h * 2]);                                  \
        mma16816(cc, al_[mi], &bh_[nj][h * 2]);                                  \
    }                                                                            \
} while (0)

    // ---- prologue ----
    ISSUE_B(0, buf0);
    asm volatile("cp.async.commit_group;" ::: "memory");
    if (nsteps > 1) ISSUE_B(1, buf1);
    asm volatile("cp.async.commit_group;" ::: "memory");
    LDGA(0, 0); STSA(buf0, 0, 0);
    LDGA(0, 1); STSA(buf0, 0, 1);

    for (int st = 0; st < nsteps; st++) {
        asm volatile("cp.async.wait_group 1;" ::: "memory");
        __syncthreads();
        unsigned bufC = (st & 1) ? buf1 : buf0;
        unsigned bufN = (st & 1) ? buf0 : buf1;
        bool pf = (st + 1) < nsteps;
        int kkEnd = min(4, (kLenC - st * KSTEP) >> 4);

        if (kkEnd == 4) {
            if (pf) LDGA(st + 1, 0);
            COMPUTE_KK(0, bufC);
            if (pf) { STSA(bufN, st + 1, 0); LDGA(st + 1, 1); }
            COMPUTE_KK(1, bufC);
            if (pf) STSA(bufN, st + 1, 1);
            COMPUTE_KK(2, bufC);
            COMPUTE_KK(3, bufC);
        } else {
            for (int kk = 0; kk < kkEnd; kk++) COMPUTE_KK(kk, bufC);
        }
        __syncthreads();
        if (st + 2 < nsteps) ISSUE_B(st + 2, bufC);
        asm volatile("cp.async.commit_group;" ::: "memory");
    }

    // ---- epilogue: atomic reduce C ----
    float* accBase = g_acc + (size_t)accIdx * B_ROWS * NCOLS;
#pragma unroll
    for (int mi = 0; mi < 2; mi++) {
        int r0 = m0 + wr * 32 + mi * 16 + (lane >> 2);
#pragma unroll
        for (int jj = 0; jj < 8; jj++) {
            int c0 = wc * 64 + jj * 8 + (lane & 3) * 2;
            atomicAdd(accBase + (size_t)r0 * NCOLS + c0,           c[mi][jj][0]);
            atomicAdd(accBase + (size_t)r0 * NCOLS + c0 + 1,       c[mi][jj][1]);
            atomicAdd(accBase + (size_t)(r0 + 8) * NCOLS + c0,     c[mi][jj][2]);
            atomicAdd(accBase + (size_t)(r0 + 8) * NCOLS + c0 + 1, c[mi][jj][3]);
        }
    }
    // ---- scal reduce across the 16 k-lanes (shfl within warp) ----
#pragma unroll
    for (int t = 0; t < 4; t++)
#pragma unroll
        for (int i = 0; i < 5; i++) {
            float v = sS[t][i];
            v += __shfl_xor_sync(0xffffffffu, v, 1);
            v += __shfl_xor_sync(0xffffffffu, v, 2);
            v += __shfl_xor_sync(0xffffffffu, v, 4);
            v += __shfl_xor_sync(0xffffffffu, v, 8);
            sS[t][i] = v;
        }
    if (aC4 == 0) {
#pragma unroll
        for (int t = 0; t < 4; t++) {
            float* d = g_scal + (size_t)(accIdx * B_ROWS + m0 + aRow0 + t * 32) * 8;
#pragma unroll
            for (int i = 0; i < 5; i++) atomicAdd(d + i, sS[t][i]);
        }
    }
#undef ISSUE_B
#undef LDGA
#undef STSA
#undef COMPUTE_KK
}

// ---------------------------------------------------------------------------
__global__ void final_kernel(const float* __restrict__ bias, float* __restrict__ out) {
    int warp = threadIdx.x >> 5, lane = threadIdx.x & 31;
    int row = blockIdx.x * 8 + warp;
    if (row >= B_ROWS) return;

    const float* aS = g_acc + (size_t)row * NCOLS;
    const float* aP = g_acc + ((size_t)B_ROWS + row) * NCOLS;
    const float* aN = g_acc + ((size_t)2 * B_ROWS + row) * NCOLS;

    float t5p = 0.f, t6p = 0.f, dgp = 0.f;
    float t5n = 0.f, t6n = 0.f, dgn = 0.f;
#pragma unroll
    for (int f = lane; f < NFEAT; f += 32) {
        float vs = aS[f],         vp = aP[f],         vn = aN[f];
        float ts = aS[NFEAT + f], tp = aP[NFEAT + f], tn = aN[NFEAT + f];
        float vxp = vs + vp, txp = ts + tp;
        float vxn = vs + vn, txn = ts + tn;
        t5p += vxp * vxp; t6p += txp * vxp; dgp += txp * txp;
        t5n += vxn * vxn; t6n += txn * vxn; dgn += txn * txn;
    }
#pragma unroll
    for (int o = 16; o; o >>= 1) {
        t5p += __shfl_down_sync(0xffffffffu, t5p, o);
        t6p += __shfl_down_sync(0xffffffffu, t6p, o);
        dgp += __shfl_down_sync(0xffffffffu, dgp, o);
        t5n += __shfl_down_sync(0xffffffffu, t5n, o);
        t6n += __shfl_down_sync(0xffffffffu, t6n, o);
        dgn += __shfl_down_sync(0xffffffffu, dgn, o);
    }
    if (lane == 0) {
        const float* sS = g_scal + (size_t)(0 * B_ROWS + row) * 8;
        const float* sP = g_scal + (size_t)(1 * B_ROWS + row) * 8;
        const float* sN = g_scal + (size_t)(2 * B_ROWS + row) * 8;

        float zvvp = sS[0] + sP[0], zttp = sS[1] + sP[1], zvtp = sS[2] + sP[2], zsp = sS[4] + sP[4];
        float zvvn = sS[0] + sN[0], zttn = sS[1] + sN[1], zvtn = sS[2] + sN[2], zsn = sS[4] + sN[4];
        float lin_neg = sS[3] + sN[3] + bias[0];

        float qp = 0.5f * (zsp * zvvp + 2.f * zsp * zttp + 2.f * zsp * zvtp
                           - 2.f * t5p - 2.f * t6p) - 0.5f * dgp;
        float qn = 0.5f * (zsn * zvvn + 2.f * zsn * zttn + 2.f * zsn * zvtn
                           - 2.f * t5n - 2.f * t6n) - 0.5f * dgn;

        out[row]          = lin_neg + qp;
        out[B_ROWS + row] = lin_neg + qn;
    }
}

// ---------------------------------------------------------------------------
extern "C" void kernel_launch(void* const* d_in, const int* in_sizes, int n_in,
                              void* d_out, int out_size) {
    const float* u     = (const float*)d_in[0];
    const float* xprev = (const float*)d_in[1];
    const float* xpos  = (const float*)d_in[2];
    const float* xneg  = (const float*)d_in[3];
    const float* V     = (const float*)d_in[4];
    const float* T     = (const float*)d_in[5];
    const float* W     = (const float*)d_in[6];
    const float* bias  = (const float*)d_in[7];
    float* out = (float*)d_out;

    cudaFuncSetAttribute(gemm_kernel, cudaFuncAttributeMaxDynamicSharedMemorySize, SMEM_DYN);

    zero_kernel<<<512, 256>>>();
    gram_kernel<<<(K_TOTAL + 7) / 8, 256>>>(V, T, W);
    prep_vt<<<dim3(KPAD / 64, 2), 256>>>(V, T);
    gemm_kernel<<<dim3(56, 16), NTHREADS, SMEM_DYN>>>(u, xprev, xpos, xneg);
    final_kernel<<<B_ROWS / 8, 256>>>(bias, out);
}

// round 9
// speedup vs baseline: 1.2833x; 1.0086x over previous
#include <cuda_runtime.h>

// ---------------------------------------------------------------------------
#define B_ROWS   2048
#define NFEAT    128
#define NCOLS    256
#define K_TOTAL  50000
#define KPAD     50560      // multiple of 64, zero padded
#define U_DIM    10000
#define X_DIM    20000
#define KSTEP    64
#define STAGE_SZ 98304      // Ahi 16K | Alo 16K | Bhi 32K | Blo 32K
#define SMEM_DYN 197632     // 2 stages + 1KB align slack
#define NTHREADS 512

// ---------------------------------------------------------------------------
__device__ unsigned short BT_hi[(size_t)NCOLS * KPAD];   // [V|T]^T bf16 hi, K-major
__device__ unsigned short BT_lo[(size_t)NCOLS * KPAD];
__device__ float g_acc[(size_t)3 * B_ROWS * NCOLS];
__device__ float g_scal[3 * B_ROWS * 8];
__device__ float4 g_gram4[K_TOTAL];                      // (vv, tt, vt, W)

// ---------------------------------------------------------------------------
__device__ __forceinline__ unsigned smem_u32(const void* p) {
    unsigned r;
    asm("{ .reg .u64 t; cvta.to.shared.u64 t, %1; cvt.u32.u64 %0, t; }" : "=r"(r) : "l"(p));
    return r;
}
__device__ __forceinline__ void split2(float f0, float f1, unsigned& h, unsigned& l) {
    unsigned b0 = __float_as_uint(f0), b1 = __float_as_uint(f1);
    h = __byte_perm(b0, b1, 0x7632);
    float l0 = f0 - __uint_as_float(b0 & 0xFFFF0000u);
    float l1 = f1 - __uint_as_float(b1 & 0xFFFF0000u);
    l = __byte_perm(__float_as_uint(l0), __float_as_uint(l1), 0x7632);
}
__device__ __forceinline__ void ldsm4(unsigned* r, unsigned a) {
    asm volatile("ldmatrix.sync.aligned.m8n8.x4.shared.b16 {%0,%1,%2,%3}, [%4];"
                 : "=r"(r[0]), "=r"(r[1]), "=r"(r[2]), "=r"(r[3]) : "r"(a));
}
__device__ __forceinline__ void mma16816(float* c, const unsigned* a, const unsigned* b) {
    asm volatile("mma.sync.aligned.m16n8k16.row.col.f32.bf16.bf16.f32 "
                 "{%0,%1,%2,%3}, {%4,%5,%6,%7}, {%8,%9}, {%0,%1,%2,%3};"
                 : "+f"(c[0]), "+f"(c[1]), "+f"(c[2]), "+f"(c[3])
                 : "r"(a[0]), "r"(a[1]), "r"(a[2]), "r"(a[3]), "r"(b[0]), "r"(b[1]));
}

// ---------------------------------------------------------------------------
__global__ void zero_kernel() {
    size_t idx = (size_t)blockIdx.x * blockDim.x + threadIdx.x;
    size_t n = (size_t)3 * B_ROWS * NCOLS;
    for (size_t i = idx; i < n; i += (size_t)gridDim.x * blockDim.x) g_acc[i] = 0.f;
    if (idx < 3 * B_ROWS * 8) g_scal[idx] = 0.f;
}

// ---------------------------------------------------------------------------
__global__ void gram_kernel(const float* __restrict__ V, const float* __restrict__ T,
                            const float* __restrict__ W) {
    int warp = threadIdx.x >> 5, lane = threadIdx.x & 31;
    int k = blockIdx.x * 8 + warp;
    if (k >= K_TOTAL) return;
    float4 v = reinterpret_cast<const float4*>(V + (size_t)k * NFEAT)[lane];
    float4 t = reinterpret_cast<const float4*>(T + (size_t)k * NFEAT)[lane];
    float vv = v.x*v.x + v.y*v.y + v.z*v.z + v.w*v.w;
    float tt = t.x*t.x + t.y*t.y + t.z*t.z + t.w*t.w;
    float vt = v.x*t.x + v.y*t.y + v.z*t.z + v.w*t.w;
#pragma unroll
    for (int o = 16; o; o >>= 1) {
        vv += __shfl_down_sync(0xffffffffu, vv, o);
        tt += __shfl_down_sync(0xffffffffu, tt, o);
        vt += __shfl_down_sync(0xffffffffu, vt, o);
    }
    if (lane == 0) g_gram4[k] = make_float4(vv, tt, vt, W[k]);
}

// ---------------------------------------------------------------------------
__global__ void prep_vt(const float* __restrict__ V, const float* __restrict__ T) {
    __shared__ float tile[64][129];
    const float* S = blockIdx.y ? T : V;
    int nBase = blockIdx.y ? NFEAT : 0;
    int k0 = blockIdx.x * 64;
    int tid = threadIdx.x;
#pragma unroll
    for (int t = 0; t < 8; t++) {
        int idx = tid + t * 256;
        int r = idx >> 5, n4 = idx & 31;
        float4 v = make_float4(0.f, 0.f, 0.f, 0.f);
        if (k0 + r < K_TOTAL)
            v = *reinterpret_cast<const float4*>(S + (size_t)(k0 + r) * NFEAT + n4 * 4);
        tile[r][n4*4+0] = v.x; tile[r][n4*4+1] = v.y;
        tile[r][n4*4+2] = v.z; tile[r][n4*4+3] = v.w;
    }
    __syncthreads();
#pragma unroll
    for (int t = 0; t < 4; t++) {
        int idx = tid + t * 256;
        int n = idx >> 3, rq = idx & 7;
        int kk = k0 + rq * 8;
        unsigned hw[4], lw[4];
#pragma unroll
        for (int j = 0; j < 4; j++)
            split2(tile[rq*8 + 2*j][n], tile[rq*8 + 2*j + 1][n], hw[j], lw[j]);
        size_t off = (size_t)(nBase + n) * KPAD + kk;
        *reinterpret_cast<uint4*>(BT_hi + off) = make_uint4(hw[0], hw[1], hw[2], hw[3]);
        *reinterpret_cast<uint4*>(BT_lo + off) = make_uint4(lw[0], lw[1], lw[2], lw[3]);
    }
}

// ---------------------------------------------------------------------------
// CTA tile 128x256, 512 threads, 16 warps (4m x 4n), warp tile 32x64.
// scal fused into A producer. grid = (37 kchunks, 16 mtiles) = 592 CTAs
// = exactly 4 waves of 148 SMs (wave-quantization fix).
// Chunk plan: u 5x2000 | xprev 10x2000 | xpos 11x1824(last 1760) | xneg same.
__global__ void __launch_bounds__(NTHREADS, 1) gemm_kernel(
    const float* __restrict__ u, const float* __restrict__ xprev,
    const float* __restrict__ xpos, const float* __restrict__ xneg)
{
    extern __shared__ char dyn[];
    unsigned sraw = smem_u32(dyn);
    unsigned sb = (sraw + 1023u) & ~1023u;
    const unsigned buf0 = sb, buf1 = sb + STAGE_SZ;

    const int tid = threadIdx.x;
    const int lane = tid & 31, warp = tid >> 5;
    const int wr = warp >> 2, wc = warp & 3;   // 4m x 4n

    int kc = blockIdx.x;
    const float* A; int lda, kLen, segOff, accIdx, kStart;
    if (kc < 5)       { A = u;     lda = U_DIM; kLen = U_DIM; segOff = 0;             accIdx = 0; kStart = kc * 2000; }
    else if (kc < 15) { A = xprev; lda = X_DIM; kLen = X_DIM; segOff = U_DIM;         accIdx = 0; kStart = (kc - 5) * 2000; }
    else if (kc < 26) { A = xpos;  lda = X_DIM; kLen = X_DIM; segOff = U_DIM + X_DIM; accIdx = 1; kStart = (kc - 15) * 1824; }
    else              { A = xneg;  lda = X_DIM; kLen = X_DIM; segOff = U_DIM + X_DIM; accIdx = 2; kStart = (kc - 26) * 1824; }
    const int chunkLen = (kc < 15) ? 2000 : 1824;
    const int m0 = blockIdx.y * 128;
    const int kLenC = min(chunkLen, kLen - kStart);   // multiple of 16
    const int nsteps = (kLenC + KSTEP - 1) / KSTEP;

    // ---- B cp.async mapping: 4096 16B tasks -> 8 per thread ----
    const unsigned short* bSrc[8]; unsigned bDst[8];
#pragma unroll
    for (int tt = 0; tt < 8; tt++) {
        int idx = tid + tt * NTHREADS;
        int plane = idx >> 11, rn = (idx >> 3) & 255, kq = idx & 7;
        const unsigned short* base = plane ? BT_lo : BT_hi;
        bSrc[tt] = base + (size_t)rn * KPAD + segOff + kStart + kq * 8;
        unsigned off = rn * 128 + kq * 16;
        bDst[tt] = 32768u + plane * 32768u + (off ^ ((off >> 3) & 0x70));
    }
    // ---- A producer mapping (fused scal): rows aRow0+{0,32,64,96}, 16 k-lanes ----
    const int aRow0 = tid >> 4, aC4 = tid & 15;
    const long l32 = (long)32 * lda;
    const float* aP0 = A + (size_t)(m0 + aRow0) * lda + kStart + aC4 * 4;
    const unsigned aSts0 = aRow0 * 128 + aC4 * 8;
    const unsigned aMsk = ((unsigned)(aRow0 & 7)) << 4;
    const float4* gP0 = g_gram4 + segOff + kStart + aC4 * 4;

    // ---- ldsm offsets (pre-swizzle) + masks ----
    unsigned aLd[2], aMk[2], bLd[4], bMk[4];
#pragma unroll
    for (int mi = 0; mi < 2; mi++) {
        int rowm = wr * 32 + mi * 16 + (lane & 15);
        aLd[mi] = rowm * 128 + (lane >> 4) * 16;
        aMk[mi] = ((unsigned)(rowm & 7)) << 4;
    }
#pragma unroll
    for (int nj = 0; nj < 4; nj++) {
        int rown = wc * 64 + nj * 16 + ((lane >> 4) << 3) + (lane & 7);
        bLd[nj] = rown * 128 + ((lane >> 3) & 1) * 16;
        bMk[nj] = ((unsigned)(rown & 7)) << 4;
    }

    float c[2][8][4];
#pragma unroll
    for (int i = 0; i < 2; i++)
#pragma unroll
        for (int j = 0; j < 8; j++)
#pragma unroll
            for (int q = 0; q < 4; q++) c[i][j][q] = 0.f;
    float sS[4][5];
#pragma unroll
    for (int t = 0; t < 4; t++)
#pragma unroll
        for (int i = 0; i < 5; i++) sS[t][i] = 0.f;
    float4 avH[2];

#define ISSUE_B(st, bufAdr) do {                                                 \
    int bo_ = (st) * KSTEP;                                                      \
    _Pragma("unroll")                                                            \
    for (int tt = 0; tt < 8; tt++) {                                             \
        unsigned d_ = (bufAdr) + bDst[tt];                                       \
        const void* s_ = (const void*)(bSrc[tt] + bo_);                          \
        asm volatile("cp.async.cg.shared.global [%0], [%1], 16;"                 \
                     :: "r"(d_), "l"(s_) : "memory");                            \
    }                                                                            \
} while (0)

#define LDGA(stA, h) do {                                                        \
    int ko_ = (stA) * KSTEP + aC4 * 4;                                           \
    _Pragma("unroll")                                                            \
    for (int t = 0; t < 2; t++) {                                                \
        if (ko_ < kLenC)                                                         \
            avH[t] = *reinterpret_cast<const float4*>(aP0 + ((h) * 2 + t) * l32 + (stA) * KSTEP); \
        else avH[t] = make_float4(0.f, 0.f, 0.f, 0.f);                           \
    }                                                                            \
} while (0)

// gram index: gP0 is one float4 per k, already offset by aC4*4 -> step offset stA*KSTEP
#define STSA(bufAdr, stA, h) do {                                                \
    int ko_ = (stA) * KSTEP + aC4 * 4;                                           \
    float4 gr_ = (ko_ < kLenC) ? gP0[(stA) * KSTEP]     : make_float4(0.f,0.f,0.f,0.f); \
    float4 g1_ = (ko_ < kLenC) ? gP0[(stA) * KSTEP + 1] : make_float4(0.f,0.f,0.f,0.f); \
    float4 g2_ = (ko_ < kLenC) ? gP0[(stA) * KSTEP + 2] : make_float4(0.f,0.f,0.f,0.f); \
    float4 g3_ = (ko_ < kLenC) ? gP0[(stA) * KSTEP + 3] : make_float4(0.f,0.f,0.f,0.f); \
    _Pragma("unroll")                                                            \
    for (int t = 0; t < 2; t++) {                                                \
        unsigned h01, l01, h23, l23;                                             \
        split2(avH[t].x, avH[t].y, h01, l01);                                    \
        split2(avH[t].z, avH[t].w, h23, l23);                                    \
        unsigned o_ = (aSts0 + ((h) * 2 + t) * 4096u) ^ aMsk;                    \
        asm volatile("st.shared.v2.u32 [%0], {%1,%2};"                           \
                     :: "r"((bufAdr) + o_), "r"(h01), "r"(h23) : "memory");      \
        asm volatile("st.shared.v2.u32 [%0], {%1,%2};"                           \
                     :: "r"((bufAdr) + 16384u + o_), "r"(l01), "r"(l23) : "memory"); \
        float* s_ = sS[(h) * 2 + t];                                             \
        s_[0] += avH[t].x * gr_.x; s_[1] += avH[t].x * gr_.y;                    \
        s_[2] += avH[t].x * gr_.z; s_[3] += avH[t].x * gr_.w; s_[4] += avH[t].x; \
        s_[0] += avH[t].y * g1_.x; s_[1] += avH[t].y * g1_.y;                    \
        s_[2] += avH[t].y * g1_.z; s_[3] += avH[t].y * g1_.w; s_[4] += avH[t].y; \
        s_[0] += avH[t].z * g2_.x; s_[1] += avH[t].z * g2_.y;                    \
        s_[2] += avH[t].z * g2_.z; s_[3] += avH[t].z * g2_.w; s_[4] += avH[t].z; \
        s_[0] += avH[t].w * g3_.x; s_[1] += avH[t].w * g3_.y;                    \
        s_[2] += avH[t].w * g3_.z; s_[3] += avH[t].w * g3_.w; s_[4] += avH[t].w; \
    }                                                                            \
} while (0)

#define COMPUTE_KK(kk, bufAdr) do {                                              \
    unsigned bh_[4][4], bl_[4][4], ah_[2][4], al_[2][4];                         \
    _Pragma("unroll")                                                            \
    for (int nj = 0; nj < 4; nj++) {                                             \
        unsigned o_ = (bLd[nj] + (kk) * 32u) ^ bMk[nj];                          \
        ldsm4(bh_[nj], (bufAdr) + 32768u + o_);                                  \
        ldsm4(bl_[nj], (bufAdr) + 65536u + o_);                                  \
    }                                                                            \
    _Pragma("unroll")                                                            \
    for (int mi = 0; mi < 2; mi++) {                                             \
        unsigned o_ = (aLd[mi] + (kk) * 32u) ^ aMk[mi];                          \
        ldsm4(ah_[mi], (bufAdr) + o_);                                           \
        ldsm4(al_[mi], (bufAdr) + 16384u + o_);                                  \
    }                                                                            \
    _Pragma("unroll")                                                            \
    for (int mi = 0; mi < 2; mi++)                                               \
    _Pragma("unroll")                                                            \
    for (int nj = 0; nj < 4; nj++)                                               \
    _Pragma("unroll")                                                            \
    for (int h = 0; h < 2; h++) {                                                \
        float* cc = c[mi][nj * 2 + h];                                           \
        mma16816(cc, ah_[mi], &bh_[nj][h * 2]);                                  \
        mma16816(cc, ah_[mi], &bl_[nj][h * 2]);                                  \
        mma16816(cc, al_[mi], &bh_[nj][h * 2]);                                  \
    }                                                                            \
} while (0)

    // ---- prologue ----
    ISSUE_B(0, buf0);
    asm volatile("cp.async.commit_group;" ::: "memory");
    if (nsteps > 1) ISSUE_B(1, buf1);
    asm volatile("cp.async.commit_group;" ::: "memory");
    LDGA(0, 0); STSA(buf0, 0, 0);
    LDGA(0, 1); STSA(buf0, 0, 1);

    for (int st = 0; st < nsteps; st++) {
        asm volatile("cp.async.wait_group 1;" ::: "memory");
        __syncthreads();
        unsigned bufC = (st & 1) ? buf1 : buf0;
        unsigned bufN = (st & 1) ? buf0 : buf1;
        bool pf = (st + 1) < nsteps;
        int kkEnd = min(4, (kLenC - st * KSTEP) >> 4);

        if (kkEnd == 4) {
            if (pf) LDGA(st + 1, 0);
            COMPUTE_KK(0, bufC);
            if (pf) { STSA(bufN, st + 1, 0); LDGA(st + 1, 1); }
            COMPUTE_KK(1, bufC);
            if (pf) STSA(bufN, st + 1, 1);
            COMPUTE_KK(2, bufC);
            COMPUTE_KK(3, bufC);
        } else {
            for (int kk = 0; kk < kkEnd; kk++) COMPUTE_KK(kk, bufC);
        }
        __syncthreads();
        if (st + 2 < nsteps) ISSUE_B(st + 2, bufC);
        asm volatile("cp.async.commit_group;" ::: "memory");
    }

    // ---- epilogue: atomic reduce C ----
    float* accBase = g_acc + (size_t)accIdx * B_ROWS * NCOLS;
#pragma unroll
    for (int mi = 0; mi < 2; mi++) {
        int r0 = m0 + wr * 32 + mi * 16 + (lane >> 2);
#pragma unroll
        for (int jj = 0; jj < 8; jj++) {
            int c0 = wc * 64 + jj * 8 + (lane & 3) * 2;
            atomicAdd(accBase + (size_t)r0 * NCOLS + c0,           c[mi][jj][0]);
            atomicAdd(accBase + (size_t)r0 * NCOLS + c0 + 1,       c[mi][jj][1]);
            atomicAdd(accBase + (size_t)(r0 + 8) * NCOLS + c0,     c[mi][jj][2]);
            atomicAdd(accBase + (size_t)(r0 + 8) * NCOLS + c0 + 1, c[mi][jj][3]);
        }
    }
    // ---- scal reduce across the 16 k-lanes ----
#pragma unroll
    for (int t = 0; t < 4; t++)
#pragma unroll
        for (int i = 0; i < 5; i++) {
            float v = sS[t][i];
            v += __shfl_xor_sync(0xffffffffu, v, 1);
            v += __shfl_xor_sync(0xffffffffu, v, 2);
            v += __shfl_xor_sync(0xffffffffu, v, 4);
            v += __shfl_xor_sync(0xffffffffu, v, 8);
            sS[t][i] = v;
        }
    if (aC4 == 0) {
#pragma unroll
        for (int t = 0; t < 4; t++) {
            float* d = g_scal + (size_t)(accIdx * B_ROWS + m0 + aRow0 + t * 32) * 8;
#pragma unroll
            for (int i = 0; i < 5; i++) atomicAdd(d + i, sS[t][i]);
        }
    }
#undef ISSUE_B
#undef LDGA
#undef STSA
#undef COMPUTE_KK
}

// ---------------------------------------------------------------------------
__global__ void final_kernel(const float* __restrict__ bias, float* __restrict__ out) {
    int warp = threadIdx.x >> 5, lane = threadIdx.x & 31;
    int row = blockIdx.x * 8 + warp;
    if (row >= B_ROWS) return;

    const float* aS = g_acc + (size_t)row * NCOLS;
    const float* aP = g_acc + ((size_t)B_ROWS + row) * NCOLS;
    const float* aN = g_acc + ((size_t)2 * B_ROWS + row) * NCOLS;

    float t5p = 0.f, t6p = 0.f, dgp = 0.f;
    float t5n = 0.f, t6n = 0.f, dgn = 0.f;
#pragma unroll
    for (int f = lane; f < NFEAT; f += 32) {
        float vs = aS[f],         vp = aP[f],         vn = aN[f];
        float ts = aS[NFEAT + f], tp = aP[NFEAT + f], tn = aN[NFEAT + f];
        float vxp = vs + vp, txp = ts + tp;
        float vxn = vs + vn, txn = ts + tn;
        t5p += vxp * vxp; t6p += txp * vxp; dgp += txp * txp;
        t5n += vxn * vxn; t6n += txn * vxn; dgn += txn * txn;
    }
#pragma unroll
    for (int o = 16; o; o >>= 1) {
        t5p += __shfl_down_sync(0xffffffffu, t5p, o);
        t6p += __shfl_down_sync(0xffffffffu, t6p, o);
        dgp += __shfl_down_sync(0xffffffffu, dgp, o);
        t5n += __shfl_down_sync(0xffffffffu, t5n, o);
        t6n += __shfl_down_sync(0xffffffffu, t6n, o);
        dgn += __shfl_down_sync(0xffffffffu, dgn, o);
    }
    if (lane == 0) {
        const float* sS = g_scal + (size_t)(0 * B_ROWS + row) * 8;
        const float* sP = g_scal + (size_t)(1 * B_ROWS + row) * 8;
        const float* sN = g_scal + (size_t)(2 * B_ROWS + row) * 8;

        float zvvp = sS[0] + sP[0], zttp = sS[1] + sP[1], zvtp = sS[2] + sP[2], zsp = sS[4] + sP[4];
        float zvvn = sS[0] + sN[0], zttn = sS[1] + sN[1], zvtn = sS[2] + sN[2], zsn = sS[4] + sN[4];
        float lin_neg = sS[3] + sN[3] + bias[0];

        float qp = 0.5f * (zsp * zvvp + 2.f * zsp * zttp + 2.f * zsp * zvtp
                           - 2.f * t5p - 2.f * t6p) - 0.5f * dgp;
        float qn = 0.5f * (zsn * zvvn + 2.f * zsn * zttn + 2.f * zsn * zvtn
                           - 2.f * t5n - 2.f * t6n) - 0.5f * dgn;

        out[row]          = lin_neg + qp;
        out[B_ROWS + row] = lin_neg + qn;
    }
}

// ---------------------------------------------------------------------------
extern "C" void kernel_launch(void* const* d_in, const int* in_sizes, int n_in,
                              void* d_out, int out_size) {
    const float* u     = (const float*)d_in[0];
    const float* xprev = (const float*)d_in[1];
    const float* xpos  = (const float*)d_in[2];
    const float* xneg  = (const float*)d_in[3];
    const float* V     = (const float*)d_in[4];
    const float* T     = (const float*)d_in[5];
    const float* W     = (const float*)d_in[6];
    const float* bias  = (const float*)d_in[7];
    float* out = (float*)d_out;

    cudaFuncSetAttribute(gemm_kernel, cudaFuncAttributeMaxDynamicSharedMemorySize, SMEM_DYN);

    zero_kernel<<<512, 256>>>();
    gram_kernel<<<(K_TOTAL + 7) / 8, 256>>>(V, T, W);
    prep_vt<<<dim3(KPAD / 64, 2), 256>>>(V, T);
    gemm_kernel<<<dim3(37, 16), NTHREADS, SMEM_DYN>>>(u, xprev, xpos, xneg);
    final_kernel<<<B_ROWS / 8, 256>>>(bias, out);
}